// round 7
// baseline (speedup 1.0000x reference)
#include <cuda_runtime.h>
#include <cuda_bf16.h>
#include <cstdint>

#define B_  16
#define P_  2048
#define H_  128
#define K_  8
#define NPTS (B_ * P_)

// ---------------- scratch (no allocations allowed) ----------------
__device__ float g_x1[NPTS * H_];
__device__ float g_x2[NPTS * H_];
__device__ float g_x3[NPTS * H_];
__device__ float g_sq[NPTS];
__device__ int   g_idx[NPTS * K_];
__device__ float g_pool[B_ * 3 * H_];

// ---------------- top-8 (smallest d2, tie -> lower index) ----------------
__device__ __forceinline__ void top8_init(float* bd, int* bi) {
#pragma unroll
    for (int m = 0; m < 8; m++) { bd[m] = __int_as_float(0x7f800000); bi[m] = 0x7fffffff; }
}

// Sorted ascending list (bd[0] best ... bd[7] worst). Static indexing only.
__device__ __forceinline__ void top8_insert(float* bd, int* bi, float d, int j) {
    if (d < bd[7] || (d == bd[7] && j < bi[7])) {
        bd[7] = d; bi[7] = j;
#pragma unroll
        for (int m = 7; m > 0; m--) {
            bool sw = (bd[m] < bd[m - 1]) || (bd[m] == bd[m - 1] && bi[m] < bi[m - 1]);
            if (!sw) break;
            float td = bd[m]; bd[m] = bd[m - 1]; bd[m - 1] = td;
            int   tj = bi[m]; bi[m] = bi[m - 1]; bi[m - 1] = tj;
        }
    }
}

// ---------------- squared norms (one warp per point) ----------------
__global__ void sqnorm_kernel(const float* __restrict__ X, float* __restrict__ sq,
                              int D, int npts) {
    int gw = (blockIdx.x * blockDim.x + threadIdx.x) >> 5;
    int lane = threadIdx.x & 31;
    if (gw >= npts) return;
    const float* xp = X + (size_t)gw * D;
    float s = 0.f;
    for (int d = lane; d < D; d += 32) { float v = xp[d]; s = fmaf(v, v, s); }
#pragma unroll
    for (int o = 16; o > 0; o >>= 1) s += __shfl_xor_sync(0xffffffffu, s, o);
    if (lane == 0) sq[gw] = s;
}

// ---------------- kNN for D=3 (one thread per query) ----------------
__global__ __launch_bounds__(256) void knn3_kernel(const float* __restrict__ X,
                                                   const float* __restrict__ sq,
                                                   int* __restrict__ idx) {
    int b = blockIdx.y;
    int q = blockIdx.x * 256 + threadIdx.x;
    const float* Xb  = X  + (size_t)b * P_ * 3;
    const float* sqb = sq + (size_t)b * P_;
    float qx = Xb[q * 3 + 0], qy = Xb[q * 3 + 1], qz = Xb[q * 3 + 2];
    float sqq = sqb[q];
    float bd[8]; int bi[8]; top8_init(bd, bi);
    __shared__ float cs[256][4];
    for (int t = 0; t < P_; t += 256) {
        int tt = threadIdx.x;
        cs[tt][0] = Xb[(t + tt) * 3 + 0];
        cs[tt][1] = Xb[(t + tt) * 3 + 1];
        cs[tt][2] = Xb[(t + tt) * 3 + 2];
        cs[tt][3] = sqb[t + tt];
        __syncthreads();
        for (int jj = 0; jj < 256; jj++) {
            float dot = qx * cs[jj][0] + qy * cs[jj][1] + qz * cs[jj][2];
            float d = sqq + cs[jj][3] - 2.f * dot;
            top8_insert(bd, bi, d, t + jj);
        }
        __syncthreads();
    }
    int* op = idx + ((size_t)b * P_ + q) * K_;
#pragma unroll
    for (int m = 0; m < 8; m++) op[m] = bi[m];
}

// ---------------- kNN for D=128 (tiled GEMM-like) ----------------
// grid (P/32, B), block 256. 32 queries per block, 2x2 register micro-tile.
__global__ __launch_bounds__(256) void knn128_kernel(const float* __restrict__ X,
                                                     const float* __restrict__ sq,
                                                     int* __restrict__ idx) {
    __shared__ float Qs[32][129];
    __shared__ float Cs[32][33];
    __shared__ float d2s[32][33];
    __shared__ float md[2048];
    __shared__ int   mi[2048];

    int b  = blockIdx.y;
    int q0 = blockIdx.x * 32;
    int tid = threadIdx.x;
    int tx = tid & 15, ty = tid >> 4;
    const float* Xb  = X  + (size_t)b * P_ * 128;
    const float* sqb = sq + (size_t)b * P_;

    for (int e = tid; e < 32 * 128; e += 256) {
        int r = e >> 7, c = e & 127;
        Qs[r][c] = Xb[(q0 + r) * 128 + c];
    }
    __syncthreads();

    int qs = tid >> 3, sl = tid & 7;       // scan role: 8 threads per query
    float sqq = sqb[q0 + qs];
    float bd[8]; int bi[8]; top8_init(bd, bi);

    for (int c0 = 0; c0 < P_; c0 += 32) {
        float a00 = 0.f, a01 = 0.f, a10 = 0.f, a11 = 0.f;
        for (int dc = 0; dc < 128; dc += 32) {
            for (int e = tid; e < 1024; e += 256) {
                int r = e >> 5, c = e & 31;
                Cs[r][c] = Xb[(c0 + r) * 128 + dc + c];
            }
            __syncthreads();
#pragma unroll
            for (int kk = 0; kk < 32; kk++) {
                float qv0 = Qs[ty][dc + kk],  qv1 = Qs[ty + 16][dc + kk];
                float cv0 = Cs[tx][kk],       cv1 = Cs[tx + 16][kk];
                a00 = fmaf(qv0, cv0, a00); a01 = fmaf(qv0, cv1, a01);
                a10 = fmaf(qv1, cv0, a10); a11 = fmaf(qv1, cv1, a11);
            }
            __syncthreads();
        }
        d2s[ty][tx]           = a00;
        d2s[ty][tx + 16]      = a01;
        d2s[ty + 16][tx]      = a10;
        d2s[ty + 16][tx + 16] = a11;
        __syncthreads();
#pragma unroll
        for (int u = 0; u < 4; u++) {
            int c = sl + u * 8;
            int j = c0 + c;
            float d = sqq + sqb[j] - 2.f * d2s[qs][c];
            top8_insert(bd, bi, d, j);
        }
        __syncthreads();
    }

    // merge 8 partial top-8 lists per query
    int base = qs * 64 + sl * 8;
#pragma unroll
    for (int m = 0; m < 8; m++) { md[base + m] = bd[m]; mi[base + m] = bi[m]; }
    __syncthreads();
    if (sl == 0) {
        float fd[8]; int fi[8]; top8_init(fd, fi);
        for (int e = 0; e < 64; e++) top8_insert(fd, fi, md[qs * 64 + e], mi[qs * 64 + e]);
        int* op = idx + ((size_t)b * P_ + q0 + qs) * K_;
#pragma unroll
        for (int m = 0; m < 8; m++) op[m] = fi[m];
    }
}

// ---------------- EdgeConv MLP ----------------
// e = [xi, xj-xi]; e@W1 = xi@(W1_hi - W1_lo) + xj@W1_lo where hi=rows[0:D), lo=rows[D:2D).
// 4 points per 256-thread block concurrently (slot=tid>>6), 2 channels per thread.
template <int D>
__global__ __launch_bounds__(256) void edgeconv_kernel(
    const float* __restrict__ xin, const int* __restrict__ idx,
    const float* __restrict__ W1, const float* __restrict__ b1,
    const float* __restrict__ W2, const float* __restrict__ b2,
    float* __restrict__ xout)
{
    const int H = H_;
    extern __shared__ float sm[];
    float* Wd  = sm;                 // D*H : W1_hi - W1_lo
    float* Wlo = Wd + D * H;         // D*H
    float* W2s = Wlo + D * H;        // H*H
    float* xib = W2s + H * H;        // 4*D
    float* xjb = xib + 4 * D;        // 4*D
    float* h1b = xjb + 4 * D;        // 4*H

    int tid  = threadIdx.x;
    int slot = tid >> 6;             // 0..3
    int hh   = tid & 63;             // channel pair index
    int ca   = hh * 2, cb = hh * 2 + 1;

    for (int e = tid; e < D * H; e += 256) {
        float a = W1[e], bv = W1[D * H + e];
        Wd[e] = a - bv; Wlo[e] = bv;
    }
    for (int e = tid; e < H * H; e += 256) W2s[e] = W2[e];
    __syncthreads();

    float bias1a = b1[ca], bias1b = b1[cb];
    float bias2a = b2[ca], bias2b = b2[cb];
    const float2* Wd2  = (const float2*)Wd;
    const float2* Wlo2 = (const float2*)Wlo;
    const float2* W22  = (const float2*)W2s;

    int pg0 = blockIdx.x * 16;       // 16 points per block
    for (int it = 0; it < 4; ++it) {
        int pg = pg0 + it * 4 + slot;          // flattened b*P + p
        const float* xi = xin + (size_t)pg * D;
        for (int d = hh; d < D; d += 64) xib[slot * D + d] = xi[d];
        __syncthreads();

        float ta = bias1a, tb = bias1b;
#pragma unroll 8
        for (int d = 0; d < D; ++d) {
            float xv = xib[slot * D + d];
            float2 w = Wd2[d * 64 + hh];
            ta = fmaf(xv, w.x, ta); tb = fmaf(xv, w.y, tb);
        }

        float acca = 0.f, accb = 0.f;
        const int* ip = idx + (size_t)pg * K_;
        for (int k = 0; k < K_; ++k) {
            int j = ip[k];
            const float* xj = xin + ((size_t)((pg & ~(P_ - 1)) + j)) * D;
            for (int d = hh; d < D; d += 64) xjb[slot * D + d] = xj[d];
            __syncthreads();

            float h1a = ta, h1bv = tb;
#pragma unroll 8
            for (int d = 0; d < D; ++d) {
                float xv = xjb[slot * D + d];
                float2 w = Wlo2[d * 64 + hh];
                h1a = fmaf(xv, w.x, h1a); h1bv = fmaf(xv, w.y, h1bv);
            }
            h1a  = fmaxf(h1a, 0.f);
            h1bv = fmaxf(h1bv, 0.f);
            h1b[slot * H + ca] = h1a;
            h1b[slot * H + cb] = h1bv;
            __syncthreads();

            float h2a = bias2a, h2b = bias2b;
#pragma unroll 8
            for (int d = 0; d < H; ++d) {
                float hv = h1b[slot * H + d];
                float2 w = W22[d * 64 + hh];
                h2a = fmaf(hv, w.x, h2a); h2b = fmaf(hv, w.y, h2b);
            }
            acca += fmaxf(h2a, 0.f);
            accb += fmaxf(h2b, 0.f);
            __syncthreads();
        }
        float2 o; o.x = acca * 0.125f; o.y = accb * 0.125f;
        ((float2*)(xout + (size_t)pg * H))[hh] = o;
        __syncthreads();
    }
}

// ---------------- mean pool over points into (B, 3H) ----------------
__global__ void pool_kernel(const float* __restrict__ x1, const float* __restrict__ x2,
                            const float* __restrict__ x3, float* __restrict__ pooled) {
    int b = blockIdx.x;
    int c = threadIdx.x;                    // 0..383
    const float* src = (c < 128) ? x1 : ((c < 256) ? x2 : x3);
    int cc = c & 127;
    float s = 0.f;
    for (int p = 0; p < P_; p++) s += src[((size_t)b * P_ + p) * H_ + cc];
    pooled[b * 384 + c] = s * (1.f / (float)P_);
}

// ---------------- head MLP: (B,384)@ (384,128) -> relu -> @(128,2) ----------------
__global__ void head_kernel(const float* __restrict__ pooled,
                            const float* __restrict__ W1, const float* __restrict__ b1,
                            const float* __restrict__ W2, const float* __restrict__ b2,
                            float* __restrict__ out) {
    int b = blockIdx.x;
    int h = threadIdx.x;                    // 0..127
    __shared__ float v[128];
    float t = b1[h];
    for (int c = 0; c < 384; c++) t = fmaf(pooled[b * 384 + c], W1[c * 128 + h], t);
    v[h] = fmaxf(t, 0.f);
    __syncthreads();
    if (h < 2) {
        float o = b2[h];
        for (int d = 0; d < 128; d++) o = fmaf(v[d], W2[d * 2 + h], o);
        out[b * 2 + h] = o;
    }
}

// ---------------- launch ----------------
extern "C" void kernel_launch(void* const* d_in, const int* in_sizes, int n_in,
                              void* d_out, int out_size) {
    const float* x     = (const float*)d_in[0];
    const float* c1W1  = (const float*)d_in[1];
    const float* c1b1  = (const float*)d_in[2];
    const float* c1W2  = (const float*)d_in[3];
    const float* c1b2  = (const float*)d_in[4];
    const float* c2W1  = (const float*)d_in[5];
    const float* c2b1  = (const float*)d_in[6];
    const float* c2W2  = (const float*)d_in[7];
    const float* c2b2  = (const float*)d_in[8];
    const float* c3W1  = (const float*)d_in[9];
    const float* c3b1  = (const float*)d_in[10];
    const float* c3W2  = (const float*)d_in[11];
    const float* c3b2  = (const float*)d_in[12];
    const float* mW1   = (const float*)d_in[13];
    const float* mb1   = (const float*)d_in[14];
    const float* mW2   = (const float*)d_in[15];
    const float* mb2   = (const float*)d_in[16];
    float* out = (float*)d_out;

    float *x1, *x2, *x3, *sqv, *pool;
    int* idxv;
    cudaGetSymbolAddress((void**)&x1,   g_x1);
    cudaGetSymbolAddress((void**)&x2,   g_x2);
    cudaGetSymbolAddress((void**)&x3,   g_x3);
    cudaGetSymbolAddress((void**)&sqv,  g_sq);
    cudaGetSymbolAddress((void**)&idxv, g_idx);
    cudaGetSymbolAddress((void**)&pool, g_pool);

    const int SMEM3   = (2 * 3 * H_ + H_ * H_ + 8 * 3 + 4 * H_) * (int)sizeof(float);
    const int SMEM128 = (2 * 128 * H_ + H_ * H_ + 8 * 128 + 4 * H_) * (int)sizeof(float);
    cudaFuncSetAttribute(edgeconv_kernel<3>,   cudaFuncAttributeMaxDynamicSharedMemorySize, SMEM3);
    cudaFuncSetAttribute(edgeconv_kernel<128>, cudaFuncAttributeMaxDynamicSharedMemorySize, SMEM128);

    // ---- layer 1 (D=3) ----
    sqnorm_kernel<<<NPTS / 8, 256>>>(x, sqv, 3, NPTS);
    knn3_kernel<<<dim3(P_ / 256, B_), 256>>>(x, sqv, idxv);
    edgeconv_kernel<3><<<NPTS / 16, 256, SMEM3>>>(x, idxv, c1W1, c1b1, c1W2, c1b2, x1);

    // ---- layer 2 (D=128) ----
    sqnorm_kernel<<<NPTS / 8, 256>>>(x1, sqv, 128, NPTS);
    knn128_kernel<<<dim3(P_ / 32, B_), 256>>>(x1, sqv, idxv);
    edgeconv_kernel<128><<<NPTS / 16, 256, SMEM128>>>(x1, idxv, c2W1, c2b1, c2W2, c2b2, x2);

    // ---- layer 3 (D=128) ----
    sqnorm_kernel<<<NPTS / 8, 256>>>(x2, sqv, 128, NPTS);
    knn128_kernel<<<dim3(P_ / 32, B_), 256>>>(x2, sqv, idxv);
    edgeconv_kernel<128><<<NPTS / 16, 256, SMEM128>>>(x2, idxv, c3W1, c3b1, c3W2, c3b2, x3);

    // ---- pool + head ----
    pool_kernel<<<B_, 384>>>(x1, x2, x3, pool);
    head_kernel<<<B_, 128>>>(pool, mW1, mb1, mW2, mb2, out);
}

// round 8
// speedup vs baseline: 2.0880x; 2.0880x over previous
#include <cuda_runtime.h>
#include <cuda_bf16.h>
#include <cstdint>

#define B_  16
#define P_  2048
#define H_  128
#define K_  8
#define NPTS (B_ * P_)

// ---------------- scratch (no allocations allowed) ----------------
__device__ float g_x1[NPTS * H_];
__device__ float g_x2[NPTS * H_];
__device__ float g_x3[NPTS * H_];
__device__ float g_T [NPTS * H_];
__device__ float g_Y [NPTS * H_];
__device__ float g_sq[NPTS];
__device__ int   g_idx[NPTS * K_];
__device__ float g_pool[B_ * 3 * H_];

// ---------------- top-8 (smallest d2, tie -> lower index) ----------------
__device__ __forceinline__ void top8_init(float* bd, int* bi) {
#pragma unroll
    for (int m = 0; m < 8; m++) { bd[m] = __int_as_float(0x7f800000); bi[m] = 0x7fffffff; }
}

__device__ __forceinline__ void top8_insert(float* bd, int* bi, float d, int j) {
    if (d < bd[7] || (d == bd[7] && j < bi[7])) {
        bd[7] = d; bi[7] = j;
#pragma unroll
        for (int m = 7; m > 0; m--) {
            bool sw = (bd[m] < bd[m - 1]) || (bd[m] == bd[m - 1] && bi[m] < bi[m - 1]);
            if (!sw) break;
            float td = bd[m]; bd[m] = bd[m - 1]; bd[m - 1] = td;
            int   tj = bi[m]; bi[m] = bi[m - 1]; bi[m - 1] = tj;
        }
    }
}

// ---------------- squared norms (one warp per point) ----------------
__global__ void sqnorm_kernel(const float* __restrict__ X, float* __restrict__ sq,
                              int D, int npts) {
    int gw = (blockIdx.x * blockDim.x + threadIdx.x) >> 5;
    int lane = threadIdx.x & 31;
    if (gw >= npts) return;
    const float* xp = X + (size_t)gw * D;
    float s = 0.f;
    for (int d = lane; d < D; d += 32) { float v = xp[d]; s = fmaf(v, v, s); }
#pragma unroll
    for (int o = 16; o > 0; o >>= 1) s += __shfl_xor_sync(0xffffffffu, s, o);
    if (lane == 0) sq[gw] = s;
}

// ---------------- kNN for D=3 (one thread per query) ----------------
__global__ __launch_bounds__(256) void knn3_kernel(const float* __restrict__ X,
                                                   const float* __restrict__ sq,
                                                   int* __restrict__ idx) {
    int b = blockIdx.y;
    int q = blockIdx.x * 256 + threadIdx.x;
    const float* Xb  = X  + (size_t)b * P_ * 3;
    const float* sqb = sq + (size_t)b * P_;
    float qx = Xb[q * 3 + 0], qy = Xb[q * 3 + 1], qz = Xb[q * 3 + 2];
    float sqq = sqb[q];
    float bd[8]; int bi[8]; top8_init(bd, bi);
    __shared__ float cs[256][4];
    for (int t = 0; t < P_; t += 256) {
        int tt = threadIdx.x;
        cs[tt][0] = Xb[(t + tt) * 3 + 0];
        cs[tt][1] = Xb[(t + tt) * 3 + 1];
        cs[tt][2] = Xb[(t + tt) * 3 + 2];
        cs[tt][3] = sqb[t + tt];
        __syncthreads();
        for (int jj = 0; jj < 256; jj++) {
            float dot = qx * cs[jj][0] + qy * cs[jj][1] + qz * cs[jj][2];
            float d = sqq + cs[jj][3] - 2.f * dot;
            top8_insert(bd, bi, d, t + jj);
        }
        __syncthreads();
    }
    int* op = idx + ((size_t)b * P_ + q) * K_;
#pragma unroll
    for (int m = 0; m < 8; m++) op[m] = bi[m];
}

// ---------------- kNN for D=128, 64x64 tiles, 4x4 micro-tile ----------------
// smem carve (floats): Qs[128*68] | Cs[32*68] | d2s[64*65] | csq[64] | md[2048] | mi[2048]
#define KNN_SMEM_FLOATS (128*68 + 32*68 + 64*65 + 64 + 2048 + 2048)
__global__ __launch_bounds__(256) void knn128_kernel(const float* __restrict__ X,
                                                     const float* __restrict__ sq,
                                                     int* __restrict__ idx) {
    extern __shared__ float sm[];
    float* Qs  = sm;                       // [d][q] stride 68
    float* Cs  = Qs + 128 * 68;            // [d][c] stride 68
    float* d2s = Cs + 32 * 68;             // [q][c] stride 65
    float* csq = d2s + 64 * 65;
    float* md  = csq + 64;
    int*   mi  = (int*)(md + 2048);
    float4* Qs4 = (float4*)Qs;
    float4* Cs4 = (float4*)Cs;

    int b  = blockIdx.y;
    int q0 = blockIdx.x * 64;
    int tid = threadIdx.x;
    int tx = tid & 15, ty = tid >> 4;
    const float* Xb  = X  + (size_t)b * P_ * 128;
    const float* sqb = sq + (size_t)b * P_;

    // load Q tile transposed: Qs[d][q]
    for (int e = tid; e < 64 * 128; e += 256) {
        int q = e >> 7, d = e & 127;
        Qs[d * 68 + q] = Xb[(q0 + q) * 128 + d];
    }

    int q_s = tid >> 2, sl = tid & 3;          // scan role: 4 lanes per query
    float sqq = sqb[q0 + q_s];
    float bd[8]; int bi[8]; top8_init(bd, bi);
    __syncthreads();

    for (int c0 = 0; c0 < P_; c0 += 64) {
        if (tid < 64) csq[tid] = sqb[c0 + tid];

        float4 acc0 = {0,0,0,0}, acc1 = {0,0,0,0}, acc2 = {0,0,0,0}, acc3 = {0,0,0,0};
        for (int dc = 0; dc < 128; dc += 32) {
            for (int e = tid; e < 2048; e += 256) {
                int c = e >> 5, d = e & 31;
                Cs[d * 68 + c] = Xb[(c0 + c) * 128 + dc + d];
            }
            __syncthreads();
#pragma unroll
            for (int kk = 0; kk < 32; kk++) {
                float4 qv = Qs4[(dc + kk) * 17 + ty];
                float4 cv = Cs4[kk * 17 + tx];
                acc0.x = fmaf(qv.x, cv.x, acc0.x); acc0.y = fmaf(qv.x, cv.y, acc0.y);
                acc0.z = fmaf(qv.x, cv.z, acc0.z); acc0.w = fmaf(qv.x, cv.w, acc0.w);
                acc1.x = fmaf(qv.y, cv.x, acc1.x); acc1.y = fmaf(qv.y, cv.y, acc1.y);
                acc1.z = fmaf(qv.y, cv.z, acc1.z); acc1.w = fmaf(qv.y, cv.w, acc1.w);
                acc2.x = fmaf(qv.z, cv.x, acc2.x); acc2.y = fmaf(qv.z, cv.y, acc2.y);
                acc2.z = fmaf(qv.z, cv.z, acc2.z); acc2.w = fmaf(qv.z, cv.w, acc2.w);
                acc3.x = fmaf(qv.w, cv.x, acc3.x); acc3.y = fmaf(qv.w, cv.y, acc3.y);
                acc3.z = fmaf(qv.w, cv.z, acc3.z); acc3.w = fmaf(qv.w, cv.w, acc3.w);
            }
            __syncthreads();
        }
        // dump 4x4 d2 micro-tile
        {
            int qb = ty * 4, cb = tx * 4;
            float* r0 = d2s + (qb + 0) * 65 + cb;
            float* r1 = d2s + (qb + 1) * 65 + cb;
            float* r2 = d2s + (qb + 2) * 65 + cb;
            float* r3 = d2s + (qb + 3) * 65 + cb;
            r0[0] = acc0.x; r0[1] = acc0.y; r0[2] = acc0.z; r0[3] = acc0.w;
            r1[0] = acc1.x; r1[1] = acc1.y; r1[2] = acc1.z; r1[3] = acc1.w;
            r2[0] = acc2.x; r2[1] = acc2.y; r2[2] = acc2.z; r2[3] = acc2.w;
            r3[0] = acc3.x; r3[1] = acc3.y; r3[2] = acc3.z; r3[3] = acc3.w;
        }
        __syncthreads();
        // scan: 4 lanes per query, 16 candidates each
#pragma unroll
        for (int u = 0; u < 16; u++) {
            int c = sl * 16 + u;
            int j = c0 + c;
            float d = sqq + csq[c] - 2.f * d2s[q_s * 65 + c];
            top8_insert(bd, bi, d, j);
        }
        __syncthreads();   // protect csq/Cs/d2s for next tile
    }

    // merge 4 partial lists per query
    int base = q_s * 32 + sl * 8;
#pragma unroll
    for (int m = 0; m < 8; m++) { md[base + m] = bd[m]; mi[base + m] = bi[m]; }
    __syncthreads();
    if (sl == 0) {
        float fd[8]; int fi[8]; top8_init(fd, fi);
        for (int e = 0; e < 32; e++) top8_insert(fd, fi, md[q_s * 32 + e], mi[q_s * 32 + e]);
        int* op = idx + ((size_t)b * P_ + q0 + q_s) * K_;
#pragma unroll
        for (int m = 0; m < 8; m++) op[m] = fi[m];
    }
}

// ---------------- pretransform, D=3: T = x@(Whi-Wlo)+b1, Y = x@Wlo ----------------
__global__ __launch_bounds__(256) void pre3_kernel(const float* __restrict__ x,
                                                   const float* __restrict__ W1,
                                                   const float* __restrict__ b1,
                                                   float* __restrict__ T,
                                                   float* __restrict__ Y) {
    int p = blockIdx.x * 8 + (threadIdx.x >> 5);
    int l = threadIdx.x & 31;
    const float4* W14 = (const float4*)W1;
    float4 t = ((const float4*)b1)[l];
    float4 y = {0.f, 0.f, 0.f, 0.f};
#pragma unroll
    for (int r = 0; r < 3; r++) {
        float  xr  = x[p * 3 + r];
        float4 whi = W14[r * 32 + l];
        float4 wlo = W14[(3 + r) * 32 + l];
        t.x = fmaf(xr, whi.x - wlo.x, t.x); t.y = fmaf(xr, whi.y - wlo.y, t.y);
        t.z = fmaf(xr, whi.z - wlo.z, t.z); t.w = fmaf(xr, whi.w - wlo.w, t.w);
        y.x = fmaf(xr, wlo.x, y.x); y.y = fmaf(xr, wlo.y, y.y);
        y.z = fmaf(xr, wlo.z, y.z); y.w = fmaf(xr, wlo.w, y.w);
    }
    ((float4*)T)[p * 32 + l] = t;
    ((float4*)Y)[p * 32 + l] = y;
}

// ---------------- pretransform, D=128 ----------------
// block 512 = 16 warps x 8 points; smem: Wd[16384] | Wlo[16384] | Xs[16*1024]
#define PRE_SMEM_FLOATS (16384 + 16384 + 16 * 1024)
__global__ __launch_bounds__(512) void pre128_kernel(const float* __restrict__ xin,
                                                     const float* __restrict__ W1,
                                                     const float* __restrict__ b1,
                                                     float* __restrict__ T,
                                                     float* __restrict__ Y) {
    extern __shared__ float sm[];
    float* Wds  = sm;
    float* Wlos = Wds + 16384;
    float* Xs   = Wlos + 16384;
    int tid = threadIdx.x;
    int warp = tid >> 5, lane = tid & 31;

    for (int e = tid; e < 16384; e += 512) {
        float hi = W1[e], lo = W1[16384 + e];
        Wds[e] = hi - lo; Wlos[e] = lo;
    }
    int p0 = blockIdx.x * 128 + warp * 8;
    float4* Xw4 = (float4*)(Xs + warp * 1024);
#pragma unroll
    for (int e = 0; e < 8; e++)
        Xw4[e * 32 + lane] = ((const float4*)xin)[(size_t)(p0 + e) * 32 + lane];
    __syncthreads();

    const float4* Wd4  = (const float4*)Wds;
    const float4* Wl4  = (const float4*)Wlos;
    const float4* Xf4  = (const float4*)(Xs + warp * 1024);

#pragma unroll 1
    for (int pass = 0; pass < 2; pass++) {
        const float4* W4 = pass ? Wl4 : Wd4;
        float4 acc[8];
#pragma unroll
        for (int e = 0; e < 8; e++) acc[e] = make_float4(0.f, 0.f, 0.f, 0.f);
        for (int d0 = 0; d0 < 128; d0 += 4) {
            float4 w0 = W4[(d0 + 0) * 32 + lane];
            float4 w1 = W4[(d0 + 1) * 32 + lane];
            float4 w2 = W4[(d0 + 2) * 32 + lane];
            float4 w3 = W4[(d0 + 3) * 32 + lane];
#pragma unroll
            for (int e = 0; e < 8; e++) {
                float4 h = Xf4[e * 32 + (d0 >> 2)];
                acc[e].x = fmaf(h.x, w0.x, acc[e].x); acc[e].y = fmaf(h.x, w0.y, acc[e].y);
                acc[e].z = fmaf(h.x, w0.z, acc[e].z); acc[e].w = fmaf(h.x, w0.w, acc[e].w);
                acc[e].x = fmaf(h.y, w1.x, acc[e].x); acc[e].y = fmaf(h.y, w1.y, acc[e].y);
                acc[e].z = fmaf(h.y, w1.z, acc[e].z); acc[e].w = fmaf(h.y, w1.w, acc[e].w);
                acc[e].x = fmaf(h.z, w2.x, acc[e].x); acc[e].y = fmaf(h.z, w2.y, acc[e].y);
                acc[e].z = fmaf(h.z, w2.z, acc[e].z); acc[e].w = fmaf(h.z, w2.w, acc[e].w);
                acc[e].x = fmaf(h.w, w3.x, acc[e].x); acc[e].y = fmaf(h.w, w3.y, acc[e].y);
                acc[e].z = fmaf(h.w, w3.z, acc[e].z); acc[e].w = fmaf(h.w, w3.w, acc[e].w);
            }
        }
        if (pass == 0) {
            float4 bb = ((const float4*)b1)[lane];
#pragma unroll
            for (int e = 0; e < 8; e++) {
                float4 o; o.x = acc[e].x + bb.x; o.y = acc[e].y + bb.y;
                o.z = acc[e].z + bb.z; o.w = acc[e].w + bb.w;
                ((float4*)T)[(size_t)(p0 + e) * 32 + lane] = o;
            }
        } else {
#pragma unroll
            for (int e = 0; e < 8; e++)
                ((float4*)Y)[(size_t)(p0 + e) * 32 + lane] = acc[e];
        }
    }
}

// ---------------- edge MLP2: out[i] = mean_k relu( relu(T[i]+Y[j_k]) @ W2 + b2 ) ----------------
// block 512 = 16 warps, 1 point per warp per iter, 4 iters -> 64 points/block
// smem: W2s[16384] | H1[16 * 1024]
#define EDGE_SMEM_FLOATS (16384 + 16 * 1024)
__global__ __launch_bounds__(512) void edgeb_kernel(const float* __restrict__ T,
                                                    const float* __restrict__ Y,
                                                    const int* __restrict__ idx,
                                                    const float* __restrict__ W2,
                                                    const float* __restrict__ b2,
                                                    float* __restrict__ xout) {
    extern __shared__ float sm[];
    float* W2s = sm;
    float* H1  = W2s + 16384;
    int tid = threadIdx.x;
    int warp = tid >> 5, lane = tid & 31;

    for (int e = tid; e < 16384; e += 512) W2s[e] = W2[e];
    __syncthreads();

    const float4* W2s4 = (const float4*)W2s;
    float4* H1w4 = (float4*)(H1 + warp * 1024);
    float4 bb = ((const float4*)b2)[lane];

#pragma unroll 1
    for (int it = 0; it < 4; it++) {
        int p = blockIdx.x * 64 + it * 16 + warp;
        int base = p & ~(P_ - 1);
        const int* ip = idx + (size_t)p * K_;
        float4 t = ((const float4*)T)[(size_t)p * 32 + lane];
#pragma unroll
        for (int e = 0; e < 8; e++) {
            int j = ip[e];
            float4 y = ((const float4*)Y)[(size_t)(base + j) * 32 + lane];
            float4 h;
            h.x = fmaxf(t.x + y.x, 0.f); h.y = fmaxf(t.y + y.y, 0.f);
            h.z = fmaxf(t.z + y.z, 0.f); h.w = fmaxf(t.w + y.w, 0.f);
            H1w4[e * 32 + lane] = h;
        }
        __syncwarp();

        float4 acc[8];
#pragma unroll
        for (int e = 0; e < 8; e++) acc[e] = make_float4(0.f, 0.f, 0.f, 0.f);
        for (int d0 = 0; d0 < 128; d0 += 4) {
            float4 w0 = W2s4[(d0 + 0) * 32 + lane];
            float4 w1 = W2s4[(d0 + 1) * 32 + lane];
            float4 w2 = W2s4[(d0 + 2) * 32 + lane];
            float4 w3 = W2s4[(d0 + 3) * 32 + lane];
#pragma unroll
            for (int e = 0; e < 8; e++) {
                float4 h = H1w4[e * 32 + (d0 >> 2)];
                acc[e].x = fmaf(h.x, w0.x, acc[e].x); acc[e].y = fmaf(h.x, w0.y, acc[e].y);
                acc[e].z = fmaf(h.x, w0.z, acc[e].z); acc[e].w = fmaf(h.x, w0.w, acc[e].w);
                acc[e].x = fmaf(h.y, w1.x, acc[e].x); acc[e].y = fmaf(h.y, w1.y, acc[e].y);
                acc[e].z = fmaf(h.y, w1.z, acc[e].z); acc[e].w = fmaf(h.y, w1.w, acc[e].w);
                acc[e].x = fmaf(h.z, w2.x, acc[e].x); acc[e].y = fmaf(h.z, w2.y, acc[e].y);
                acc[e].z = fmaf(h.z, w2.z, acc[e].z); acc[e].w = fmaf(h.z, w2.w, acc[e].w);
                acc[e].x = fmaf(h.w, w3.x, acc[e].x); acc[e].y = fmaf(h.w, w3.y, acc[e].y);
                acc[e].z = fmaf(h.w, w3.z, acc[e].z); acc[e].w = fmaf(h.w, w3.w, acc[e].w);
            }
        }
        float4 s = {0.f, 0.f, 0.f, 0.f};
#pragma unroll
        for (int e = 0; e < 8; e++) {
            s.x += fmaxf(acc[e].x + bb.x, 0.f);
            s.y += fmaxf(acc[e].y + bb.y, 0.f);
            s.z += fmaxf(acc[e].z + bb.z, 0.f);
            s.w += fmaxf(acc[e].w + bb.w, 0.f);
        }
        s.x *= 0.125f; s.y *= 0.125f; s.z *= 0.125f; s.w *= 0.125f;
        ((float4*)xout)[(size_t)p * 32 + lane] = s;
        __syncwarp();
    }
}

// ---------------- mean pool over points into (B, 3H) ----------------
__global__ void pool_kernel(const float* __restrict__ x1, const float* __restrict__ x2,
                            const float* __restrict__ x3, float* __restrict__ pooled) {
    int b = blockIdx.x;
    int c = threadIdx.x;                    // 0..383
    const float* src = (c < 128) ? x1 : ((c < 256) ? x2 : x3);
    int cc = c & 127;
    float s = 0.f;
    for (int p = 0; p < P_; p++) s += src[((size_t)b * P_ + p) * H_ + cc];
    pooled[b * 384 + c] = s * (1.f / (float)P_);
}

// ---------------- head MLP ----------------
__global__ void head_kernel(const float* __restrict__ pooled,
                            const float* __restrict__ W1, const float* __restrict__ b1,
                            const float* __restrict__ W2, const float* __restrict__ b2,
                            float* __restrict__ out) {
    int b = blockIdx.x;
    int h = threadIdx.x;                    // 0..127
    __shared__ float v[128];
    float t = b1[h];
    for (int c = 0; c < 384; c++) t = fmaf(pooled[b * 384 + c], W1[c * 128 + h], t);
    v[h] = fmaxf(t, 0.f);
    __syncthreads();
    if (h < 2) {
        float o = b2[h];
        for (int d = 0; d < 128; d++) o = fmaf(v[d], W2[d * 2 + h], o);
        out[b * 2 + h] = o;
    }
}

// ---------------- launch ----------------
extern "C" void kernel_launch(void* const* d_in, const int* in_sizes, int n_in,
                              void* d_out, int out_size) {
    const float* x     = (const float*)d_in[0];
    const float* c1W1  = (const float*)d_in[1];
    const float* c1b1  = (const float*)d_in[2];
    const float* c1W2  = (const float*)d_in[3];
    const float* c1b2  = (const float*)d_in[4];
    const float* c2W1  = (const float*)d_in[5];
    const float* c2b1  = (const float*)d_in[6];
    const float* c2W2  = (const float*)d_in[7];
    const float* c2b2  = (const float*)d_in[8];
    const float* c3W1  = (const float*)d_in[9];
    const float* c3b1  = (const float*)d_in[10];
    const float* c3W2  = (const float*)d_in[11];
    const float* c3b2  = (const float*)d_in[12];
    const float* mW1   = (const float*)d_in[13];
    const float* mb1   = (const float*)d_in[14];
    const float* mW2   = (const float*)d_in[15];
    const float* mb2   = (const float*)d_in[16];
    float* out = (float*)d_out;

    float *x1, *x2, *x3, *T, *Y, *sqv, *pool;
    int* idxv;
    cudaGetSymbolAddress((void**)&x1,   g_x1);
    cudaGetSymbolAddress((void**)&x2,   g_x2);
    cudaGetSymbolAddress((void**)&x3,   g_x3);
    cudaGetSymbolAddress((void**)&T,    g_T);
    cudaGetSymbolAddress((void**)&Y,    g_Y);
    cudaGetSymbolAddress((void**)&sqv,  g_sq);
    cudaGetSymbolAddress((void**)&idxv, g_idx);
    cudaGetSymbolAddress((void**)&pool, g_pool);

    const int KNN_SMEM  = KNN_SMEM_FLOATS  * (int)sizeof(float);
    const int PRE_SMEM  = PRE_SMEM_FLOATS  * (int)sizeof(float);
    const int EDGE_SMEM = EDGE_SMEM_FLOATS * (int)sizeof(float);
    cudaFuncSetAttribute(knn128_kernel, cudaFuncAttributeMaxDynamicSharedMemorySize, KNN_SMEM);
    cudaFuncSetAttribute(pre128_kernel, cudaFuncAttributeMaxDynamicSharedMemorySize, PRE_SMEM);
    cudaFuncSetAttribute(edgeb_kernel,  cudaFuncAttributeMaxDynamicSharedMemorySize, EDGE_SMEM);

    // ---- layer 1 (D=3) ----
    sqnorm_kernel<<<NPTS / 8, 256>>>(x, sqv, 3, NPTS);
    knn3_kernel<<<dim3(P_ / 256, B_), 256>>>(x, sqv, idxv);
    pre3_kernel<<<NPTS / 8, 256>>>(x, c1W1, c1b1, T, Y);
    edgeb_kernel<<<NPTS / 64, 512, EDGE_SMEM>>>(T, Y, idxv, c1W2, c1b2, x1);

    // ---- layer 2 (D=128) ----
    sqnorm_kernel<<<NPTS / 8, 256>>>(x1, sqv, 128, NPTS);
    knn128_kernel<<<dim3(P_ / 64, B_), 256, KNN_SMEM>>>(x1, sqv, idxv);
    pre128_kernel<<<NPTS / 128, 512, PRE_SMEM>>>(x1, c2W1, c2b1, T, Y);
    edgeb_kernel<<<NPTS / 64, 512, EDGE_SMEM>>>(T, Y, idxv, c2W2, c2b2, x2);

    // ---- layer 3 (D=128) ----
    sqnorm_kernel<<<NPTS / 8, 256>>>(x2, sqv, 128, NPTS);
    knn128_kernel<<<dim3(P_ / 64, B_), 256, KNN_SMEM>>>(x2, sqv, idxv);
    pre128_kernel<<<NPTS / 128, 512, PRE_SMEM>>>(x2, c3W1, c3b1, T, Y);
    edgeb_kernel<<<NPTS / 64, 512, EDGE_SMEM>>>(T, Y, idxv, c3W2, c3b2, x3);

    // ---- pool + head ----
    pool_kernel<<<B_, 384>>>(x1, x2, x3, pool);
    head_kernel<<<B_, 128>>>(pool, mW1, mb1, mW2, mb2, out);
}